// round 1
// baseline (speedup 1.0000x reference)
#include <cuda_runtime.h>
#include <cstdint>

#define BATCH 32
#define CIN   256
#define COUT  256
#define HH_   56
#define WW_   56
#define NPOS  (BATCH*HH_*WW_)   // 100352 spatial positions

// Packed sign bits. Scratch as __device__ globals (no allocs allowed).
__device__ uint4 g_xpack[NPOS * 2];        // per pos: 8 x uint32 (256 channels)
__device__ uint4 g_wpack[COUT * 9 * 2];    // per (cout, tap): 8 x uint32

// ---------------------------------------------------------------------------
// Pack x: NCHW float -> [pos][8 words] bitmask, bit=1 iff x >= 0
// ---------------------------------------------------------------------------
__global__ void pack_x_kernel(const float* __restrict__ x) {
    int pos = blockIdx.x * blockDim.x + threadIdx.x;
    if (pos >= NPOS) return;
    int b  = pos / (HH_ * WW_);
    int hw = pos - b * (HH_ * WW_);
    const float* xp = x + (size_t)b * CIN * HH_ * WW_ + hw;

    uint32_t wds[8];
    for (int k = 0; k < 8; ++k) {
        uint32_t wd = 0;
        #pragma unroll
        for (int i = 0; i < 32; ++i) {
            float v = xp[(size_t)(k * 32 + i) * (HH_ * WW_)];
            wd |= (v >= 0.0f ? 1u : 0u) << i;
        }
        wds[k] = wd;
    }
    g_xpack[pos * 2 + 0] = make_uint4(wds[0], wds[1], wds[2], wds[3]);
    g_xpack[pos * 2 + 1] = make_uint4(wds[4], wds[5], wds[6], wds[7]);
}

// ---------------------------------------------------------------------------
// Pack weight: OIHW float -> [cout*9+tap][8 words]
// ---------------------------------------------------------------------------
__global__ void pack_w_kernel(const float* __restrict__ wgt) {
    int idx = blockIdx.x * blockDim.x + threadIdx.x;  // cout*9 + tap
    if (idx >= COUT * 9) return;
    int cout = idx / 9;
    int tap  = idx - cout * 9;
    const float* wp = wgt + (size_t)cout * CIN * 9 + tap;

    uint32_t wds[8];
    for (int k = 0; k < 8; ++k) {
        uint32_t wd = 0;
        #pragma unroll
        for (int i = 0; i < 32; ++i) {
            float v = wp[(size_t)(k * 32 + i) * 9];
            wd |= (v >= 0.0f ? 1u : 0u) << i;
        }
        wds[k] = wd;
    }
    g_wpack[idx * 2 + 0] = make_uint4(wds[0], wds[1], wds[2], wds[3]);
    g_wpack[idx * 2 + 1] = make_uint4(wds[4], wds[5], wds[6], wds[7]);
}

__device__ __forceinline__ int popc8(uint4 a, uint4 b) {
    return __popc(a.x) + __popc(a.y) + __popc(a.z) + __popc(a.w)
         + __popc(b.x) + __popc(b.y) + __popc(b.z) + __popc(b.w);
}

// ---------------------------------------------------------------------------
// Binary conv: each block = one (b, h) row x 32 couts.
// 224 threads: ct = tid&7 (4 couts each), wt = tid>>3 (2 w positions each).
// ---------------------------------------------------------------------------
__global__ void __launch_bounds__(224)
bconv_kernel(const float* __restrict__ bias, float* __restrict__ out) {
    const int cg  = blockIdx.x;   // 0..7 -> 32 couts
    const int h   = blockIdx.y;   // 0..55
    const int b   = blockIdx.z;   // 0..31
    const int tid = threadIdx.x;

    __shared__ uint4 xs[3][58][2];   // rows h-1..h+1, cols -1..56 (zero pad)
    __shared__ uint4 ws[32][9][2];

    // Load x rows (zero for out-of-range)
    for (int i = tid; i < 3 * 58 * 2; i += 224) {
        int r   = i / 116;
        int rem = i - r * 116;
        int col = rem >> 1;
        int j   = rem & 1;
        int hh  = h - 1 + r;
        int wc  = col - 1;
        uint4 v = make_uint4(0u, 0u, 0u, 0u);
        if (hh >= 0 && hh < HH_ && wc >= 0 && wc < WW_)
            v = g_xpack[(((b * HH_) + hh) * WW_ + wc) * 2 + j];
        xs[r][col][j] = v;
    }
    const int cbase = cg * 32;
    for (int i = tid; i < 32 * 9 * 2; i += 224) {
        int c   = i / 18;
        int rem = i - c * 18;
        int t   = rem >> 1;
        int j   = rem & 1;
        ws[c][t][j] = g_wpack[((cbase + c) * 9 + t) * 2 + j];
    }
    __syncthreads();

    const int ct = tid & 7;    // 0..7 -> couts ct*4 .. ct*4+3
    const int wt = tid >> 3;   // 0..27
    const int w0 = wt * 2;     // outputs at w0, w0+1

    int acc0[4] = {0, 0, 0, 0};
    int acc1[4] = {0, 0, 0, 0};

    #pragma unroll
    for (int dh = 0; dh < 3; ++dh) {
        int hh = h - 1 + dh;
        if (hh < 0 || hh >= HH_) continue;   // uniform per block
        #pragma unroll
        for (int dw = 0; dw < 3; ++dw) {
            uint4 xa0 = xs[dh][w0 + dw][0];
            uint4 xa1 = xs[dh][w0 + dw][1];
            uint4 xb0 = xs[dh][w0 + dw + 1][0];
            uint4 xb1 = xs[dh][w0 + dw + 1][1];
            #pragma unroll
            for (int c = 0; c < 4; ++c) {
                uint4 wv0 = ws[ct * 4 + c][dh * 3 + dw][0];
                uint4 wv1 = ws[ct * 4 + c][dh * 3 + dw][1];
                acc0[c] += __popc(xa0.x ^ wv0.x) + __popc(xa0.y ^ wv0.y)
                         + __popc(xa0.z ^ wv0.z) + __popc(xa0.w ^ wv0.w)
                         + __popc(xa1.x ^ wv1.x) + __popc(xa1.y ^ wv1.y)
                         + __popc(xa1.z ^ wv1.z) + __popc(xa1.w ^ wv1.w);
                acc1[c] += __popc(xb0.x ^ wv0.x) + __popc(xb0.y ^ wv0.y)
                         + __popc(xb0.z ^ wv0.z) + __popc(xb0.w ^ wv0.w)
                         + __popc(xb1.x ^ wv1.x) + __popc(xb1.y ^ wv1.y)
                         + __popc(xb1.z ^ wv1.z) + __popc(xb1.w ^ wv1.w);
            }
        }
    }

    // Boundary correction: acc included popc(w) for taps whose x column was
    // the zero pad; the true contribution of those taps is 0.
    int corr0[4] = {0, 0, 0, 0};
    int corr1[4] = {0, 0, 0, 0};
    if (w0 == 0) {
        #pragma unroll
        for (int dh = 0; dh < 3; ++dh) {
            int hh = h - 1 + dh;
            if (hh < 0 || hh >= HH_) continue;
            #pragma unroll
            for (int c = 0; c < 4; ++c)
                corr0[c] += popc8(ws[ct * 4 + c][dh * 3 + 0][0],
                                  ws[ct * 4 + c][dh * 3 + 0][1]);
        }
    }
    if (w0 + 1 == WW_ - 1) {
        #pragma unroll
        for (int dh = 0; dh < 3; ++dh) {
            int hh = h - 1 + dh;
            if (hh < 0 || hh >= HH_) continue;
            #pragma unroll
            for (int c = 0; c < 4; ++c)
                corr1[c] += popc8(ws[ct * 4 + c][dh * 3 + 2][0],
                                  ws[ct * 4 + c][dh * 3 + 2][1]);
        }
    }

    const int nrows  = 3 - (h == 0) - (h == HH_ - 1);
    const int ncols0 = (w0 == 0) ? 2 : 3;
    const int ncols1 = (w0 + 1 == WW_ - 1) ? 2 : 3;

    #pragma unroll
    for (int c = 0; c < 4; ++c) {
        int cout = cbase + ct * 4 + c;
        float bv = __ldg(&bias[cout]);
        int dot0 = CIN * nrows * ncols0 - 2 * (acc0[c] - corr0[c]);
        int dot1 = CIN * nrows * ncols1 - 2 * (acc1[c] - corr1[c]);
        float2 o = make_float2((float)dot0 + bv, (float)dot1 + bv);
        *(float2*)(out + ((size_t)(b * COUT + cout) * HH_ + h) * WW_ + w0) = o;
    }
}

// ---------------------------------------------------------------------------
extern "C" void kernel_launch(void* const* d_in, const int* in_sizes, int n_in,
                              void* d_out, int out_size) {
    const float* x    = (const float*)d_in[0];
    const float* wgt  = (const float*)d_in[1];
    const float* bias = (const float*)d_in[2];
    float* out = (float*)d_out;

    pack_x_kernel<<<(NPOS + 255) / 256, 256>>>(x);
    pack_w_kernel<<<(COUT * 9 + 255) / 256, 256>>>(wgt);

    dim3 grid(COUT / 32, HH_, BATCH);
    bconv_kernel<<<grid, 224>>>(bias, out);
}

// round 2
// speedup vs baseline: 1.0022x; 1.0022x over previous
#include <cuda_runtime.h>
#include <cstdint>

#define BATCH 32
#define CIN   256
#define COUT  256
#define HH_   56
#define WW_   56
#define NPOS  (BATCH*HH_*WW_)   // 100352 spatial positions

// Packed sign bits. Scratch as __device__ globals (no allocs allowed).
__device__ uint4 g_xpack[NPOS * 2];        // per pos: 8 x uint32 (256 channels)
__device__ uint4 g_wpack[COUT * 9 * 2];    // per (cout, tap): 8 x uint32

// ---------------------------------------------------------------------------
// Pack x: NCHW float -> [pos][8 words] bitmask, bit=1 iff x >= 0
// ---------------------------------------------------------------------------
__global__ void pack_x_kernel(const float* __restrict__ x) {
    int pos = blockIdx.x * blockDim.x + threadIdx.x;
    if (pos >= NPOS) return;
    int b  = pos / (HH_ * WW_);
    int hw = pos - b * (HH_ * WW_);
    const float* xp = x + (size_t)b * CIN * HH_ * WW_ + hw;

    uint32_t wds[8];
    for (int k = 0; k < 8; ++k) {
        uint32_t wd = 0;
        #pragma unroll
        for (int i = 0; i < 32; ++i) {
            float v = xp[(size_t)(k * 32 + i) * (HH_ * WW_)];
            wd |= (v >= 0.0f ? 1u : 0u) << i;
        }
        wds[k] = wd;
    }
    g_xpack[pos * 2 + 0] = make_uint4(wds[0], wds[1], wds[2], wds[3]);
    g_xpack[pos * 2 + 1] = make_uint4(wds[4], wds[5], wds[6], wds[7]);
}

// ---------------------------------------------------------------------------
// Pack weight: OIHW float -> [cout*9+tap][8 words]
// ---------------------------------------------------------------------------
__global__ void pack_w_kernel(const float* __restrict__ wgt) {
    int idx = blockIdx.x * blockDim.x + threadIdx.x;  // cout*9 + tap
    if (idx >= COUT * 9) return;
    int cout = idx / 9;
    int tap  = idx - cout * 9;
    const float* wp = wgt + (size_t)cout * CIN * 9 + tap;

    uint32_t wds[8];
    for (int k = 0; k < 8; ++k) {
        uint32_t wd = 0;
        #pragma unroll
        for (int i = 0; i < 32; ++i) {
            float v = wp[(size_t)(k * 32 + i) * 9];
            wd |= (v >= 0.0f ? 1u : 0u) << i;
        }
        wds[k] = wd;
    }
    g_wpack[idx * 2 + 0] = make_uint4(wds[0], wds[1], wds[2], wds[3]);
    g_wpack[idx * 2 + 1] = make_uint4(wds[4], wds[5], wds[6], wds[7]);
}

__device__ __forceinline__ int popc8(uint4 a, uint4 b) {
    return __popc(a.x) + __popc(a.y) + __popc(a.z) + __popc(a.w)
         + __popc(b.x) + __popc(b.y) + __popc(b.z) + __popc(b.w);
}

// ---------------------------------------------------------------------------
// Binary conv: each block = one (b, h) row x 32 couts.
// 224 threads: ct = tid&7 (4 couts each), wt = tid>>3 (2 w positions each).
// ---------------------------------------------------------------------------
__global__ void __launch_bounds__(224)
bconv_kernel(const float* __restrict__ bias, float* __restrict__ out) {
    const int cg  = blockIdx.x;   // 0..7 -> 32 couts
    const int h   = blockIdx.y;   // 0..55
    const int b   = blockIdx.z;   // 0..31
    const int tid = threadIdx.x;

    __shared__ uint4 xs[3][58][2];   // rows h-1..h+1, cols -1..56 (zero pad)
    __shared__ uint4 ws[32][9][2];

    // Load x rows (zero for out-of-range)
    for (int i = tid; i < 3 * 58 * 2; i += 224) {
        int r   = i / 116;
        int rem = i - r * 116;
        int col = rem >> 1;
        int j   = rem & 1;
        int hh  = h - 1 + r;
        int wc  = col - 1;
        uint4 v = make_uint4(0u, 0u, 0u, 0u);
        if (hh >= 0 && hh < HH_ && wc >= 0 && wc < WW_)
            v = g_xpack[(((b * HH_) + hh) * WW_ + wc) * 2 + j];
        xs[r][col][j] = v;
    }
    const int cbase = cg * 32;
    for (int i = tid; i < 32 * 9 * 2; i += 224) {
        int c   = i / 18;
        int rem = i - c * 18;
        int t   = rem >> 1;
        int j   = rem & 1;
        ws[c][t][j] = g_wpack[((cbase + c) * 9 + t) * 2 + j];
    }
    __syncthreads();

    const int ct = tid & 7;    // 0..7 -> couts ct*4 .. ct*4+3
    const int wt = tid >> 3;   // 0..27
    const int w0 = wt * 2;     // outputs at w0, w0+1

    int acc0[4] = {0, 0, 0, 0};
    int acc1[4] = {0, 0, 0, 0};

    #pragma unroll
    for (int dh = 0; dh < 3; ++dh) {
        int hh = h - 1 + dh;
        if (hh < 0 || hh >= HH_) continue;   // uniform per block
        #pragma unroll
        for (int dw = 0; dw < 3; ++dw) {
            uint4 xa0 = xs[dh][w0 + dw][0];
            uint4 xa1 = xs[dh][w0 + dw][1];
            uint4 xb0 = xs[dh][w0 + dw + 1][0];
            uint4 xb1 = xs[dh][w0 + dw + 1][1];
            #pragma unroll
            for (int c = 0; c < 4; ++c) {
                uint4 wv0 = ws[ct * 4 + c][dh * 3 + dw][0];
                uint4 wv1 = ws[ct * 4 + c][dh * 3 + dw][1];
                acc0[c] += __popc(xa0.x ^ wv0.x) + __popc(xa0.y ^ wv0.y)
                         + __popc(xa0.z ^ wv0.z) + __popc(xa0.w ^ wv0.w)
                         + __popc(xa1.x ^ wv1.x) + __popc(xa1.y ^ wv1.y)
                         + __popc(xa1.z ^ wv1.z) + __popc(xa1.w ^ wv1.w);
                acc1[c] += __popc(xb0.x ^ wv0.x) + __popc(xb0.y ^ wv0.y)
                         + __popc(xb0.z ^ wv0.z) + __popc(xb0.w ^ wv0.w)
                         + __popc(xb1.x ^ wv1.x) + __popc(xb1.y ^ wv1.y)
                         + __popc(xb1.z ^ wv1.z) + __popc(xb1.w ^ wv1.w);
            }
        }
    }

    // Boundary correction: acc included popc(w) for taps whose x column was
    // the zero pad; the true contribution of those taps is 0.
    int corr0[4] = {0, 0, 0, 0};
    int corr1[4] = {0, 0, 0, 0};
    if (w0 == 0) {
        #pragma unroll
        for (int dh = 0; dh < 3; ++dh) {
            int hh = h - 1 + dh;
            if (hh < 0 || hh >= HH_) continue;
            #pragma unroll
            for (int c = 0; c < 4; ++c)
                corr0[c] += popc8(ws[ct * 4 + c][dh * 3 + 0][0],
                                  ws[ct * 4 + c][dh * 3 + 0][1]);
        }
    }
    if (w0 + 1 == WW_ - 1) {
        #pragma unroll
        for (int dh = 0; dh < 3; ++dh) {
            int hh = h - 1 + dh;
            if (hh < 0 || hh >= HH_) continue;
            #pragma unroll
            for (int c = 0; c < 4; ++c)
                corr1[c] += popc8(ws[ct * 4 + c][dh * 3 + 2][0],
                                  ws[ct * 4 + c][dh * 3 + 2][1]);
        }
    }

    const int nrows  = 3 - (h == 0) - (h == HH_ - 1);
    const int ncols0 = (w0 == 0) ? 2 : 3;
    const int ncols1 = (w0 + 1 == WW_ - 1) ? 2 : 3;

    #pragma unroll
    for (int c = 0; c < 4; ++c) {
        int cout = cbase + ct * 4 + c;
        float bv = __ldg(&bias[cout]);
        int dot0 = CIN * nrows * ncols0 - 2 * (acc0[c] - corr0[c]);
        int dot1 = CIN * nrows * ncols1 - 2 * (acc1[c] - corr1[c]);
        float2 o = make_float2((float)dot0 + bv, (float)dot1 + bv);
        *(float2*)(out + ((size_t)(b * COUT + cout) * HH_ + h) * WW_ + w0) = o;
    }
}

// ---------------------------------------------------------------------------
extern "C" void kernel_launch(void* const* d_in, const int* in_sizes, int n_in,
                              void* d_out, int out_size) {
    const float* x    = (const float*)d_in[0];
    const float* wgt  = (const float*)d_in[1];
    const float* bias = (const float*)d_in[2];
    float* out = (float*)d_out;

    pack_x_kernel<<<(NPOS + 255) / 256, 256>>>(x);
    pack_w_kernel<<<(COUT * 9 + 255) / 256, 256>>>(wgt);

    dim3 grid(COUT / 32, HH_, BATCH);
    bconv_kernel<<<grid, 224>>>(bias, out);
}